// round 16
// baseline (speedup 1.0000x reference)
#include <cuda_runtime.h>

// Fixed dataset: B=16384, S=8, D=128, P=65536
#define SB 8
#define DD 128
#define MAX_ROWS (16384 * SB)
#define HIB_BLOCKS 4096
#define HIB_WARPS 4              // warps per block (128 threads)
#define MAX_BLOCKS 16384
#define EPSV 1e-6f
#define LOG2E 1.4426950408889634f
#define LN2F  0.6931471805599453f

// int8 mirror of z, scale 8: z_i8 = round(z * 8). Row = 128 bytes, item = 1KB.
__device__ unsigned g_zi8[(size_t)MAX_ROWS * DD / 4];   // 16 MB
__device__ int g_inorm[MAX_ROWS];                       // int row norms (sum of squares)
__device__ float g_block_sums[MAX_BLOCKS];

__device__ __forceinline__ float ex2f(float x) {
    float y; asm("ex2.approx.ftz.f32 %0, %1;" : "=f"(y) : "f"(x)); return y;
}
__device__ __forceinline__ float lg2f(float x) {
    float y; asm("lg2.approx.ftz.f32 %0, %1;" : "=f"(y) : "f"(x)); return y;
}
__device__ __forceinline__ float rcpf(float x) {
    float y; asm("rcp.approx.ftz.f32 %0, %1;" : "=f"(y) : "f"(x)); return y;
}

// ---------------------------------------------------------------------------
// Kernel 1: fused fp32 -> int8 convert + int row norms (proven, 13.4us).
// ---------------------------------------------------------------------------
__global__ void __launch_bounds__(256) convnorm_kernel(const float4* __restrict__ z4, int rows) {
    const float MAGIC = 12582912.0f;  // 1.5 * 2^23
    int warp = (blockIdx.x * 256 + threadIdx.x) >> 5;
    int lane = threadIdx.x & 31;
    int r0 = warp * 4;
    if (r0 >= rows) return;

    float4 v[4];
#pragma unroll
    for (int k = 0; k < 4; k++) v[k] = z4[(size_t)(r0 + k) * 32 + lane];

#pragma unroll
    for (int k = 0; k < 4; k++) {
        int row = r0 + k;
        unsigned b0 = __float_as_uint(fmaf(v[k].x, 8.0f, MAGIC));
        unsigned b1 = __float_as_uint(fmaf(v[k].y, 8.0f, MAGIC));
        unsigned b2 = __float_as_uint(fmaf(v[k].z, 8.0f, MAGIC));
        unsigned b3 = __float_as_uint(fmaf(v[k].w, 8.0f, MAGIC));
        unsigned lo = __byte_perm(b0, b1, 0x0040);
        unsigned hi = __byte_perm(b2, b3, 0x0040);
        unsigned pk = __byte_perm(lo, hi, 0x5410);      // 4 packed signed int8
        g_zi8[(size_t)row * 32 + lane] = pk;

        int nrm = __dp4a((int)pk, (int)pk, 0);          // exact sum of squares
        nrm = __reduce_add_sync(0xffffffffu, nrm);      // single REDUX
        if (lane == 0) g_inorm[row] = nrm;
    }
}

// ---------------------------------------------------------------------------
// 16-byte dp4a dot: exact int32.
// ---------------------------------------------------------------------------
__device__ __forceinline__ int dot16(uint4 a, uint4 b) {
    int s;
    s = __dp4a((int)a.x, (int)b.x, 0);
    s = __dp4a((int)a.y, (int)b.y, s);
    s = __dp4a((int)a.z, (int)b.z, s);
    s = __dp4a((int)a.w, (int)b.w, s);
    return s;
}

// ---------------------------------------------------------------------------
// Multi-value int butterfly stage over lane-bit B (R11-verified).
// ---------------------------------------------------------------------------
template <int B, int HALF>
__device__ __forceinline__ void bstage_i(int* acc, int lane) {
    bool hi = (lane & B) != 0;
#pragma unroll
    for (int t = 0; t < HALF; t++) {
        int send = hi ? acc[t] : acc[t + HALF];
        int keep = hi ? acc[t + HALF] : acc[t];
        acc[t] = keep + __shfl_xor_sync(0xffffffffu, send, B);
    }
}

// ---------------------------------------------------------------------------
// Log2-domain epilogue for one matrix's two per-lane d2 values.
// ---------------------------------------------------------------------------
__device__ __forceinline__ float epilogue2(int d0, int d1, float a2, float b2,
                                           int neg) {
    float res = 0.0f;
#pragma unroll
    for (int c = 0; c < 2; c++) {
        float y2 = fmaf(-a2, (float)(c ? d1 : d0), b2);   // (beta - a*d2)*log2e
        if (!neg) {
            float sg = rcpf(1.0f + ex2f(-y2));            // sigmoid(y0)
            res -= lg2f(sg + EPSV);
        } else {
            float sg = rcpf(1.0f + ex2f(y2));             // sigmoid(-y0)
            res -= lg2f(sg - EPSV);
        }
    }
    return res;
}

// ---------------------------------------------------------------------------
// Compute TWO units from one 4KB stage, fully interleaved so unit-1's dp4a
// hides unit-0's shuffle-chain latency and vice versa.
// Stage layout: [A0 1KB | B0 1KB | A1 1KB | B1 1KB].
// R11-verified per-unit layout: t = lane&7 owns k-chunk; q = lane>>3; after
// butterfly lane holds dot(i=t, j=2q+c). Gram-form d2 exact.
// ---------------------------------------------------------------------------
__device__ __forceinline__ float compute_batch(const uint4* __restrict__ S,
                                               bool have1,
                                               const int* __restrict__ nc,
                                               float a2, float b2, int neg,
                                               int lane, int t, int q) {
    const uint4* A0 = S;
    const uint4* B0 = S + 64;
    const uint4* A1 = S + 128;
    const uint4* B1 = S + 192;

    uint4 b00 = B0[(2 * q + 0) * 8 + t];
    uint4 b01 = B0[(2 * q + 1) * 8 + t];
    uint4 b10, b11;
    if (have1) {
        b10 = B1[(2 * q + 0) * 8 + t];
        b11 = B1[(2 * q + 1) * 8 + t];
    }

    int acc0[16], acc1[16];
#pragma unroll
    for (int i = 0; i < SB; i++) {
        uint4 av0 = A0[i * 8 + t];
        acc0[i * 2 + 0] = dot16(av0, b00);
        acc0[i * 2 + 1] = dot16(av0, b01);
        if (have1) {
            uint4 av1 = A1[i * 8 + t];
            acc1[i * 2 + 0] = dot16(av1, b10);
            acc1[i * 2 + 1] = dot16(av1, b11);
        }
    }

    // interleaved butterfly stages: the two chains overlap in the scheduler
    bstage_i<4, 8>(acc0, lane);
    if (have1) bstage_i<4, 8>(acc1, lane);
    bstage_i<2, 4>(acc0, lane);
    if (have1) bstage_i<2, 4>(acc1, lane);
    bstage_i<1, 2>(acc0, lane);
    if (have1) bstage_i<1, 2>(acc1, lane);

    float res = epilogue2(nc[0] + nc[1] - 2 * acc0[0],
                          nc[0] + nc[2] - 2 * acc0[1], a2, b2, neg);
    if (have1)
        res += epilogue2(nc[3] + nc[4] - 2 * acc1[0],
                         nc[3] + nc[5] - 2 * acc1[1], a2, b2, neg);
    return res;
}

// ---------------------------------------------------------------------------
// Kernel 2: main HIB criterion. Persistent warps over MATRIX UNITS, batched
// 2 units per pipeline stage (u and u+NU share parity -> neg warp-uniform,
// same id arrays). Double-buffered 4KB stages: ONE commit/wait/syncwarp and
// one loop iteration per 2 units -> half the pipeline overhead, and the two
// units' compute interleaves for ILP.
// ---------------------------------------------------------------------------
__global__ void __launch_bounds__(128) hib_kernel(
    const float* __restrict__ alpha_p,
    const float* __restrict__ beta_p,
    const int* __restrict__ ap, const int* __restrict__ pp,
    const int* __restrict__ an, const int* __restrict__ nn,
    int P)
{
    __shared__ __align__(16) unsigned char sbuf[HIB_WARPS][2][4096];
    __shared__ float ws[HIB_WARPS];

    int lane = threadIdx.x & 31;
    int wib  = threadIdx.x >> 5;
    int gu   = blockIdx.x * HIB_WARPS + wib;      // first unit for this warp
    const int NU = HIB_BLOCKS * HIB_WARPS;        // unit stride (even!)
    int nU = 2 * P;                               // total matrix units
    int t = lane & 7;
    int q = lane >> 3;
    int neg = gu & 1;                             // warp-uniform parity

    float beta = __ldg(beta_p);
    float a = log1pf(__expf(__ldg(alpha_p)));     // softplus(alpha)
    float a2 = a * (LOG2E / 64.0f);               // fold log2e and scale^-2
    float b2 = beta * LOG2E;

    const char* zb = reinterpret_cast<const char*>(g_zi8);
    unsigned sbase = (unsigned)__cvta_generic_to_shared(&sbuf[wib][0][0]);
    unsigned co = (unsigned)(lane * 16);          // per-lane copy offset

    const int* A_ids = neg ? an : ap;
    const int* B_ids = neg ? nn : pp;

    int ncur[6], nnxt[6];
#pragma unroll
    for (int k = 0; k < 6; k++) { ncur[k] = 0; nnxt[k] = 0; }

    // Issue one unit's 2KB (A slot + B slot) at byte offset OFF within stage S,
    // and prefetch its 3 norms into N[0..2].
#define ISSUE_UNIT(U, S, OFF, N)                                                \
    {                                                                           \
        int pr = (U) >> 1;                                                      \
        int ia = __ldg(A_ids + pr), ib = __ldg(B_ids + pr);                     \
        const char* sA = zb + (size_t)ia * 1024;                                \
        const char* sB = zb + (size_t)ib * 1024;                                \
        unsigned d = sbase + (S) * 4096 + (OFF);                                \
        asm volatile("cp.async.cg.shared.global [%0], [%1], 16;" :: "r"(d + co), "l"(sA + co)); \
        asm volatile("cp.async.cg.shared.global [%0], [%1], 16;" :: "r"(d + co + 512), "l"(sA + co + 512)); \
        asm volatile("cp.async.cg.shared.global [%0], [%1], 16;" :: "r"(d + co + 1024), "l"(sB + co)); \
        asm volatile("cp.async.cg.shared.global [%0], [%1], 16;" :: "r"(d + co + 1536), "l"(sB + co + 512)); \
        (N)[0] = __ldg(g_inorm + ia * SB + t);                                  \
        (N)[1] = __ldg(g_inorm + ib * SB + 2 * q);                              \
        (N)[2] = __ldg(g_inorm + ib * SB + 2 * q + 1);                          \
    }

    // Issue batch (U, U+NU) into stage S with ONE commit.
#define ISSUE_BATCH(U, S, N)                                                    \
    {                                                                           \
        if ((U) < nU)      ISSUE_UNIT((U),      S, 0,    N);                    \
        if ((U) + NU < nU) ISSUE_UNIT((U) + NU, S, 2048, (N) + 3);              \
        asm volatile("cp.async.commit_group;" ::: "memory");                    \
    }

    // ---- prologue: fill stage 0 with the first batch ----
    if (gu < nU) ISSUE_BATCH(gu, 0, ncur);

    float total = 0.0f;
    int s = 0;
    const int STEP = 2 * NU;

    for (int u = gu; u < nU; u += STEP) {
        if (u + STEP < nU) {
            ISSUE_BATCH(u + STEP, s ^ 1, nnxt);
            asm volatile("cp.async.wait_group 1;" ::: "memory");
        } else {
            asm volatile("cp.async.wait_group 0;" ::: "memory");
        }
        __syncwarp();   // publishes all lanes' cp.async data for stage s

        bool have1 = (u + NU) < nU;
        const uint4* S4 = reinterpret_cast<const uint4*>(&sbuf[wib][s][0]);
        total += compute_batch(S4, have1, ncur, a2, b2, neg, lane, t, q);

        s ^= 1;
#pragma unroll
        for (int k = 0; k < 6; k++) ncur[k] = nnxt[k];
    }
#undef ISSUE_BATCH
#undef ISSUE_UNIT

    total *= LN2F;   // log2 -> natural log

    // warp-reduce per-lane partial sums
#pragma unroll
    for (int m = 16; m; m >>= 1) total += __shfl_xor_sync(0xffffffffu, total, m);

    if (lane == 0) ws[wib] = total;
    __syncthreads();
    if (threadIdx.x == 0) {
        float sum = 0.0f;
#pragma unroll
        for (int w = 0; w < HIB_WARPS; w++) sum += ws[w];
        g_block_sums[blockIdx.x] = sum;
    }
}

// ---------------------------------------------------------------------------
// Kernel 3: deterministic finalize — sum block partials in double, scale.
// ---------------------------------------------------------------------------
__global__ void __launch_bounds__(1024) finalize_kernel(float* out, int nblocks, int P) {
    double s = 0.0;
    for (int i = threadIdx.x; i < nblocks; i += 1024) s += (double)g_block_sums[i];
#pragma unroll
    for (int m = 16; m; m >>= 1) s += __shfl_xor_sync(0xffffffffu, s, m);
    __shared__ double sm[32];
    int lane = threadIdx.x & 31;
    int w = threadIdx.x >> 5;
    if (lane == 0) sm[w] = s;
    __syncthreads();
    if (w == 0) {
        double v = sm[lane];
#pragma unroll
        for (int m = 16; m; m >>= 1) v += __shfl_xor_sync(0xffffffffu, v, m);
        if (lane == 0) out[0] = (float)(v / ((double)P * 64.0));
    }
}

// ---------------------------------------------------------------------------
extern "C" void kernel_launch(void* const* d_in, const int* in_sizes, int n_in,
                              void* d_out, int out_size) {
    const float* z     = (const float*)d_in[0];
    const float* alpha = (const float*)d_in[1];
    const float* beta  = (const float*)d_in[2];
    const int* ap = (const int*)d_in[3];
    const int* pp = (const int*)d_in[4];
    const int* an = (const int*)d_in[5];
    const int* nn = (const int*)d_in[6];

    int P = in_sizes[3];
    int rows = in_sizes[0] / DD;  // B * S
    if (rows > MAX_ROWS) rows = MAX_ROWS;

    int nwarps  = (rows + 3) / 4;                 // one warp per 4 rows
    int cblocks = (nwarps + 7) / 8;

    convnorm_kernel<<<cblocks, 256>>>((const float4*)z, rows);
    hib_kernel<<<HIB_BLOCKS, 128>>>(alpha, beta, ap, pp, an, nn, P);
    finalize_kernel<<<1, 1024>>>((float*)d_out, HIB_BLOCKS, P);
}

// round 17
// speedup vs baseline: 1.2576x; 1.2576x over previous
#include <cuda_runtime.h>

// Fixed dataset: B=16384, S=8, D=128, P=65536
#define SB 8
#define DD 128
#define MAX_ROWS (16384 * SB)
#define HIB_BLOCKS 4096
#define HIB_WARPS 4              // warps per block (128 threads)
#define MAX_BLOCKS 16384
#define EPSV 1e-6f
#define LOG2E 1.4426950408889634f
#define LN2F  0.6931471805599453f

// int8 mirror of z, scale 8: z_i8 = round(z * 8). Row = 128 bytes, item = 1KB.
__device__ unsigned g_zi8[(size_t)MAX_ROWS * DD / 4];   // 16 MB
__device__ int g_inorm[MAX_ROWS];                       // int row norms (sum of squares)
__device__ float g_block_sums[MAX_BLOCKS];

__device__ __forceinline__ float ex2f(float x) {
    float y; asm("ex2.approx.ftz.f32 %0, %1;" : "=f"(y) : "f"(x)); return y;
}
__device__ __forceinline__ float lg2f(float x) {
    float y; asm("lg2.approx.ftz.f32 %0, %1;" : "=f"(y) : "f"(x)); return y;
}
__device__ __forceinline__ float rcpf(float x) {
    float y; asm("rcp.approx.ftz.f32 %0, %1;" : "=f"(y) : "f"(x)); return y;
}

// ---------------------------------------------------------------------------
// Kernel 1: fused fp32 -> int8 convert + int row norms (proven, 13.4us;
// at the practical DRAM roofline already).
// ---------------------------------------------------------------------------
__global__ void __launch_bounds__(256) convnorm_kernel(const float4* __restrict__ z4, int rows) {
    const float MAGIC = 12582912.0f;  // 1.5 * 2^23
    int warp = (blockIdx.x * 256 + threadIdx.x) >> 5;
    int lane = threadIdx.x & 31;
    int r0 = warp * 4;
    if (r0 >= rows) return;

    float4 v[4];
#pragma unroll
    for (int k = 0; k < 4; k++) v[k] = z4[(size_t)(r0 + k) * 32 + lane];

#pragma unroll
    for (int k = 0; k < 4; k++) {
        int row = r0 + k;
        unsigned b0 = __float_as_uint(fmaf(v[k].x, 8.0f, MAGIC));
        unsigned b1 = __float_as_uint(fmaf(v[k].y, 8.0f, MAGIC));
        unsigned b2 = __float_as_uint(fmaf(v[k].z, 8.0f, MAGIC));
        unsigned b3 = __float_as_uint(fmaf(v[k].w, 8.0f, MAGIC));
        unsigned lo = __byte_perm(b0, b1, 0x0040);
        unsigned hi = __byte_perm(b2, b3, 0x0040);
        unsigned pk = __byte_perm(lo, hi, 0x5410);      // 4 packed signed int8
        g_zi8[(size_t)row * 32 + lane] = pk;

        int nrm = __dp4a((int)pk, (int)pk, 0);          // exact sum of squares
        nrm = __reduce_add_sync(0xffffffffu, nrm);      // single REDUX
        if (lane == 0) g_inorm[row] = nrm;
    }
}

// ---------------------------------------------------------------------------
// 16-byte dp4a dot: exact int32.
// ---------------------------------------------------------------------------
__device__ __forceinline__ int dot16(uint4 a, uint4 b) {
    int s;
    s = __dp4a((int)a.x, (int)b.x, 0);
    s = __dp4a((int)a.y, (int)b.y, s);
    s = __dp4a((int)a.z, (int)b.z, s);
    s = __dp4a((int)a.w, (int)b.w, s);
    return s;
}

// ---------------------------------------------------------------------------
// Compute one 8x8 matrix from a 2KB stage (A slot 1KB + B slot 1KB).
// XOR-SKEWED, SELECT-FREE butterfly: lane (q = lane>>3, t = lane&7) deposits
// the chunk-t partial of dot(i, 2q+r) into slot (i^t)*2 + r. Then each stage
// is uniformly acc[k] += shfl_xor(acc[k+H], B) -- 2 instr per element, no
// selects (partner slot k+H of lane t^B holds the SAME value index k^t).
// Final: acc[r] = full dot(i=t, j=2q+r), identical mapping to R11/R15 ->
// same norm indexing, bit-identical integer d2.
// Epilogue branchless: x = fmaf(a2s, d, b2s); term = -lg2(rcp(1+ex2(x))+epss).
// ---------------------------------------------------------------------------
__device__ __forceinline__ float compute_unit(const uint4* __restrict__ S4,
                                              int na, int nb0, int nb1,
                                              float a2s, float b2s, float epss,
                                              int t, int q) {
    const uint4* As = S4;         // 64 uint4
    const uint4* Bs = S4 + 64;

    uint4 Bv0 = Bs[(2 * q + 0) * 8 + t];
    uint4 Bv1 = Bs[(2 * q + 1) * 8 + t];

    int acc[16];
#pragma unroll
    for (int si = 0; si < 8; si++) {
        uint4 av = As[((si ^ t) << 3) + t];   // row si^t, col t: conflict-free
        acc[si * 2 + 0] = dot16(av, Bv0);
        acc[si * 2 + 1] = dot16(av, Bv1);
    }

    // select-free skewed butterfly: 14 shfl+add pairs total
#pragma unroll
    for (int k = 0; k < 8; k++) acc[k] += __shfl_xor_sync(0xffffffffu, acc[k + 8], 4);
#pragma unroll
    for (int k = 0; k < 4; k++) acc[k] += __shfl_xor_sync(0xffffffffu, acc[k + 4], 2);
#pragma unroll
    for (int k = 0; k < 2; k++) acc[k] += __shfl_xor_sync(0xffffffffu, acc[k + 2], 1);

    int d0 = na + nb0 - 2 * acc[0];
    int d1 = na + nb1 - 2 * acc[1];

    float x0 = fmaf(a2s, (float)d0, b2s);
    float x1 = fmaf(a2s, (float)d1, b2s);
    float s0 = rcpf(1.0f + ex2f(x0));
    float s1 = rcpf(1.0f + ex2f(x1));
    return -lg2f(s0 + epss) - lg2f(s1 + epss);
}

// ---------------------------------------------------------------------------
// Issue one unit's 2KB (A slot + B slot) into stage S and prefetch norms.
// ---------------------------------------------------------------------------
#define ISSUE_UNIT(U, S, NA, NB0, NB1)                                          \
    {                                                                           \
        int pr = (U) >> 1;                                                      \
        int ia = __ldg(A_ids + pr), ib = __ldg(B_ids + pr);                     \
        const char* sA = zb + (size_t)ia * 1024;                                \
        const char* sB = zb + (size_t)ib * 1024;                                \
        unsigned d = sbase + (S) * 2048;                                        \
        asm volatile("cp.async.cg.shared.global [%0], [%1], 16;" :: "r"(d + co), "l"(sA + co)); \
        asm volatile("cp.async.cg.shared.global [%0], [%1], 16;" :: "r"(d + co + 512), "l"(sA + co + 512)); \
        asm volatile("cp.async.cg.shared.global [%0], [%1], 16;" :: "r"(d + co + 1024), "l"(sB + co)); \
        asm volatile("cp.async.cg.shared.global [%0], [%1], 16;" :: "r"(d + co + 1536), "l"(sB + co + 512)); \
        asm volatile("cp.async.commit_group;" ::: "memory");                    \
        NA  = __ldg(g_inorm + ia * SB + t);                                     \
        NB0 = __ldg(g_inorm + ib * SB + 2 * q);                                 \
        NB1 = __ldg(g_inorm + ib * SB + 2 * q + 1);                             \
    }

// common per-kernel setup
#define HIB_SETUP                                                               \
    int lane = threadIdx.x & 31;                                                \
    int wib  = threadIdx.x >> 5;                                                \
    int gu   = blockIdx.x * HIB_WARPS + wib;                                    \
    const int NU = HIB_BLOCKS * HIB_WARPS;                                      \
    int t = lane & 7;                                                           \
    int q = lane >> 3;                                                          \
    int neg = gu & 1;                                                           \
    float beta = __ldg(beta_p);                                                 \
    float a = log1pf(__expf(__ldg(alpha_p)));                                   \
    float a2 = a * (LOG2E / 64.0f);                                             \
    float b2 = beta * LOG2E;                                                    \
    float a2s  = neg ? -a2 : a2;                                                \
    float b2s  = neg ? b2 : -b2;                                                \
    float epss = neg ? -EPSV : EPSV;                                            \
    const char* zb = reinterpret_cast<const char*>(g_zi8);                      \
    unsigned sbase = (unsigned)__cvta_generic_to_shared(&sbuf[wib][0][0]);      \
    unsigned co = (unsigned)(lane * 16);                                        \
    const int* A_ids = neg ? an : ap;                                           \
    const int* B_ids = neg ? nn : pp

#define HIB_EPILOG                                                              \
    total *= LN2F;                                                              \
    _Pragma("unroll")                                                           \
    for (int m = 16; m; m >>= 1) total += __shfl_xor_sync(0xffffffffu, total, m); \
    if (lane == 0) ws[wib] = total;                                             \
    __syncthreads();                                                            \
    if (threadIdx.x == 0) {                                                     \
        float sum = 0.0f;                                                       \
        _Pragma("unroll")                                                       \
        for (int w = 0; w < HIB_WARPS; w++) sum += ws[w];                       \
        g_block_sums[blockIdx.x] = sum;                                         \
    }

// ---------------------------------------------------------------------------
// Kernel 2a: FIXED-TRIP specialization (nU == TRIPS*NU): fully unrolled
// depth-3 pipeline; stage indices it%3 and tail wait_group guards are
// compile-time, so no rotation movs and no bounds checks at all.
// ---------------------------------------------------------------------------
template <int TRIPS>
__global__ void __launch_bounds__(128) hib_kernel_fixed(
    const float* __restrict__ alpha_p,
    const float* __restrict__ beta_p,
    const int* __restrict__ ap, const int* __restrict__ pp,
    const int* __restrict__ an, const int* __restrict__ nn)
{
    __shared__ __align__(16) unsigned char sbuf[HIB_WARPS][3][2048];
    __shared__ float ws[HIB_WARPS];
    HIB_SETUP;

    int na[3], nb0[3], nb1[3];

    // prologue: stages 0 and 1
    ISSUE_UNIT(gu,          0, na[0], nb0[0], nb1[0]);
    ISSUE_UNIT(gu + NU,     1, na[1], nb0[1], nb1[1]);

    float total = 0.0f;
#pragma unroll
    for (int it = 0; it < TRIPS; it++) {
        const int sc = it % 3;
        if (it + 2 < TRIPS) {
            const int sn = (it + 2) % 3;
            ISSUE_UNIT(gu + (it + 2) * NU, sn, na[sn], nb0[sn], nb1[sn]);
            asm volatile("cp.async.wait_group 2;" ::: "memory");
        } else if (it + 1 < TRIPS) {
            asm volatile("cp.async.wait_group 1;" ::: "memory");
        } else {
            asm volatile("cp.async.wait_group 0;" ::: "memory");
        }
        __syncwarp();
        const uint4* S4 = reinterpret_cast<const uint4*>(&sbuf[wib][sc][0]);
        total += compute_unit(S4, na[sc], nb0[sc], nb1[sc], a2s, b2s, epss, t, q);
    }

    HIB_EPILOG;
}

// ---------------------------------------------------------------------------
// Kernel 2b: generic fallback (arbitrary P), R15-proven loop structure.
// ---------------------------------------------------------------------------
__global__ void __launch_bounds__(128) hib_kernel_gen(
    const float* __restrict__ alpha_p,
    const float* __restrict__ beta_p,
    const int* __restrict__ ap, const int* __restrict__ pp,
    const int* __restrict__ an, const int* __restrict__ nn,
    int P)
{
    __shared__ __align__(16) unsigned char sbuf[HIB_WARPS][3][2048];
    __shared__ float ws[HIB_WARPS];
    HIB_SETUP;
    int nU = 2 * P;

    int na0 = 0, nb00 = 0, nb01 = 0;
    int na1 = 0, nb10 = 0, nb11 = 0;
    int na2, nb20, nb21;

    if (gu < nU)      ISSUE_UNIT(gu,      0, na0, nb00, nb01);
    if (gu + NU < nU) ISSUE_UNIT(gu + NU, 1, na1, nb10, nb11);

    float total = 0.0f;
    int s0 = 0, s1 = 1, s2 = 2;

    for (int u = gu; u < nU; u += NU) {
        if (u + 2 * NU < nU) {
            ISSUE_UNIT(u + 2 * NU, s2, na2, nb20, nb21);
            asm volatile("cp.async.wait_group 2;" ::: "memory");
        } else if (u + NU < nU) {
            asm volatile("cp.async.wait_group 1;" ::: "memory");
        } else {
            asm volatile("cp.async.wait_group 0;" ::: "memory");
        }
        __syncwarp();
        const uint4* S4 = reinterpret_cast<const uint4*>(&sbuf[wib][s0][0]);
        total += compute_unit(S4, na0, nb00, nb01, a2s, b2s, epss, t, q);

        int tmp = s0; s0 = s1; s1 = s2; s2 = tmp;
        na0 = na1; nb00 = nb10; nb01 = nb11;
        na1 = na2; nb10 = nb20; nb11 = nb21;
    }

    HIB_EPILOG;
}

// ---------------------------------------------------------------------------
// Kernel 3: deterministic finalize — sum block partials in double, scale.
// ---------------------------------------------------------------------------
__global__ void __launch_bounds__(1024) finalize_kernel(float* out, int nblocks, int P) {
    double s = 0.0;
    for (int i = threadIdx.x; i < nblocks; i += 1024) s += (double)g_block_sums[i];
#pragma unroll
    for (int m = 16; m; m >>= 1) s += __shfl_xor_sync(0xffffffffu, s, m);
    __shared__ double sm[32];
    int lane = threadIdx.x & 31;
    int w = threadIdx.x >> 5;
    if (lane == 0) sm[w] = s;
    __syncthreads();
    if (w == 0) {
        double v = sm[lane];
#pragma unroll
        for (int m = 16; m; m >>= 1) v += __shfl_xor_sync(0xffffffffu, v, m);
        if (lane == 0) out[0] = (float)(v / ((double)P * 64.0));
    }
}

// ---------------------------------------------------------------------------
extern "C" void kernel_launch(void* const* d_in, const int* in_sizes, int n_in,
                              void* d_out, int out_size) {
    const float* z     = (const float*)d_in[0];
    const float* alpha = (const float*)d_in[1];
    const float* beta  = (const float*)d_in[2];
    const int* ap = (const int*)d_in[3];
    const int* pp = (const int*)d_in[4];
    const int* an = (const int*)d_in[5];
    const int* nn = (const int*)d_in[6];

    int P = in_sizes[3];
    int rows = in_sizes[0] / DD;  // B * S
    if (rows > MAX_ROWS) rows = MAX_ROWS;

    int nwarps  = (rows + 3) / 4;                 // one warp per 4 rows
    int cblocks = (nwarps + 7) / 8;

    convnorm_kernel<<<cblocks, 256>>>((const float4*)z, rows);

    const int NU = HIB_BLOCKS * HIB_WARPS;
    if (2 * P == 8 * NU) {
        hib_kernel_fixed<8><<<HIB_BLOCKS, 128>>>(alpha, beta, ap, pp, an, nn);
    } else {
        hib_kernel_gen<<<HIB_BLOCKS, 128>>>(alpha, beta, ap, pp, an, nn, P);
    }
    finalize_kernel<<<1, 1024>>>((float*)d_out, HIB_BLOCKS, P);
}